// round 5
// baseline (speedup 1.0000x reference)
#include <cuda_runtime.h>
#include <cstdint>

#define Bsz 8
#define Nn 1024
#define Ee 256
#define Dm 64
#define Hh 4
#define DH 16

// ---------------- device scratch (transposed layouts: [c][n]) ----------------
__device__ float d_qk[2][Bsz][Hh][DH][Nn];        // q, k  transposed
__device__ float d_e [4][Bsz][Hh][Ee][DH];        // eq, ek, ceq, cek
__device__ float d_g [2][2][Bsz][Hh][DH][Nn];     // [branch][q|k][b][h][c][n]; gq pre-scaled 1/8

// ---------------- K1: emb -> q,k (stores transposed) ----------------
__global__ void k_qk(const float* __restrict__ x,
                     const float* __restrict__ W_emb, const float* __restrict__ b_emb,
                     const float* __restrict__ W_q,   const float* __restrict__ b_q,
                     const float* __restrict__ W_k,   const float* __restrict__ b_k) {
    int bn  = blockIdx.x;
    int tid = threadIdx.x;         // 0..63
    __shared__ float emb[64];
    float x0 = x[bn * 2 + 0];
    float x1 = x[bn * 2 + 1];
    emb[tid] = x0 * W_emb[tid] + x1 * W_emb[64 + tid] + b_emb[tid];
    __syncthreads();
    float q = b_q[tid], k = b_k[tid];
#pragma unroll
    for (int j = 0; j < 64; ++j) {
        float e = emb[j];
        q = fmaf(e, W_q[j * 64 + tid], q);
        k = fmaf(e, W_k[j * 64 + tid], k);
    }
    int b = bn >> 10, n = bn & 1023;
    int h = tid >> 4, c = tid & 15;
    d_qk[0][b][h][c][n] = q;
    d_qk[1][b][h][c][n] = k;
}

// ---------------- K2: edge projections ----------------
__global__ void k_edge(const float* __restrict__ edge, const float* __restrict__ cedge,
                       const float* __restrict__ W_eq,  const float* __restrict__ b_eq,
                       const float* __restrict__ W_ek,  const float* __restrict__ b_ek,
                       const float* __restrict__ W_ceq, const float* __restrict__ b_ceq,
                       const float* __restrict__ W_cek, const float* __restrict__ b_cek) {
    int i = blockIdx.x * blockDim.x + threadIdx.x;
    int c = i & 15;
    int r = (i >> 4) & 8191;
    int t = i >> 17;
    const float* src = (t < 2 ? edge : cedge) + r * 16;
    const float* W; const float* bb;
    if      (t == 0) { W = W_eq;  bb = b_eq;  }
    else if (t == 1) { W = W_ek;  bb = b_ek;  }
    else if (t == 2) { W = W_ceq; bb = b_ceq; }
    else             { W = W_cek; bb = b_cek; }
    float a = bb[c];
#pragma unroll
    for (int j = 0; j < 16; ++j) a = fmaf(src[j], W[j * 16 + c], a);
    (&d_e[0][0][0][0][0])[i] = a;
}

// ---------------- K3: gq/gk (transposed out) + div, one pass over G ----------------
// grid: 2br * 8b * 16ntile = 256 blocks; 1024 threads = 16 c x 64 n
__global__ void __launch_bounds__(1024, 2)
k_gextra(const float* __restrict__ G, const float* __restrict__ CG) {
    int bid = blockIdx.x;
    int nt = bid & 15;  bid >>= 4;
    int b  = bid & 7;   bid >>= 3;
    int br = bid;
    int tid = threadIdx.x;
    int c    = tid >> 6;        // 0..15  (constant within warp -> broadcast)
    int nloc = tid & 63;        // 0..63  (consecutive within warp)
    int nbase = nt * 64;

    const float* Gm  = (br ? CG : G) + (size_t)b * Ee * Nn;
    const float* eqb = &d_e[br * 2 + 0][b][0][0][0];   // [h][e][c]
    const float* ekb = &d_e[br * 2 + 1][b][0][0][0];

    __shared__ float sg[16][64];
    __shared__ float seq[4][16][16];
    __shared__ float sek[4][16][16];

    float aq[4] = {0.f, 0.f, 0.f, 0.f};
    float ak[4] = {0.f, 0.f, 0.f, 0.f};
    float gsum = 0.f;

    for (int e0 = 0; e0 < Ee; e0 += 16) {
        __syncthreads();
        {
            int se = tid >> 6, sn = tid & 63;
            sg[se][sn] = Gm[(size_t)(e0 + se) * Nn + nbase + sn];
            int sh = tid >> 8, see = (tid >> 4) & 15, sc = tid & 15;
            seq[sh][see][sc] = eqb[(sh * Ee + e0 + see) * DH + sc];
            sek[sh][see][sc] = ekb[(sh * Ee + e0 + see) * DH + sc];
        }
        __syncthreads();
#pragma unroll
        for (int ee = 0; ee < 16; ++ee) {
            float g = sg[ee][nloc];
            gsum += g;
#pragma unroll
            for (int h = 0; h < 4; ++h) {
                aq[h] = fmaf(g, seq[h][ee][c], aq[h]);
                ak[h] = fmaf(g, sek[h][ee][c], ak[h]);
            }
        }
    }
    float rd = 1.0f / gsum;
    int n = nbase + nloc;
#pragma unroll
    for (int h = 0; h < 4; ++h) {
        float q = d_qk[0][b][h][c][n];
        float k = d_qk[1][b][h][c][n];
        d_g[br][0][b][h][c][n] = (q + aq[h] * rd) * 0.125f;   // fold 1/sqrt(64)
        d_g[br][1][b][h][c][n] = (k + ak[h] * rd);
    }
}

// ---------------- K4: scores + softmax, outer-product register tiling ----------------
// grid: 2br*8b*4h*64chunk(16 rows) = 4096 blocks; 256 threads.
// Thread (tr, tc): tr = tid>>7 (2 row-groups of 8), tc = tid&127 (128 col-groups).
// Each thread: 8 rows x 8 cols (cols tc*4..+3 and 512+tc*4..+3). 64 independent accums.
__global__ void __launch_bounds__(256, 2)
k_attn(float* __restrict__ out) {
    int bid = blockIdx.x;
    int chunk = bid & 63;  bid >>= 6;
    int h     = bid & 3;   bid >>= 2;
    int b     = bid & 7;   bid >>= 3;
    int br    = bid;
    int rbase = chunk * 16;

    const float* gqT = &d_g[br][0][b][h][0][0];   // [c][n]
    const float* gkT = &d_g[br][1][b][h][0][0];   // [c][n]

    extern __shared__ float KT[];                 // [16][1024] = 64 KB
    __shared__ float QT[16][16];
    __shared__ float red[8][8];                   // [warp][row]

    int tid = threadIdx.x;
    // stage K^T: fully coalesced float4, conflict-free STS
    for (int i = tid; i < 4096; i += 256) {
        int c  = i >> 8;
        int n4 = (i & 255) << 2;
        *(float4*)&KT[c * 1024 + n4] = *(const float4*)(gkT + c * 1024 + n4);
    }
    // stage Q^T (16x16)
    if (tid < 256) {
        int c = tid >> 4, r = tid & 15;
        QT[c][r] = gqT[c * 1024 + rbase + r];
    }
    __syncthreads();

    int tr = tid >> 7;          // 0..1
    int tc = tid & 127;         // 0..127
    int warp = tid >> 5, lane = tid & 31;

    float s[64];
#pragma unroll
    for (int i = 0; i < 64; ++i) s[i] = 0.f;

#pragma unroll
    for (int c = 0; c < 16; ++c) {
        float4 qa = *(const float4*)&QT[c][tr * 8];       // broadcast
        float4 qb = *(const float4*)&QT[c][tr * 8 + 4];
        float4 ka = *(const float4*)&KT[c * 1024 + tc * 4];
        float4 kb = *(const float4*)&KT[c * 1024 + 512 + tc * 4];
        float qv[8] = {qa.x, qa.y, qa.z, qa.w, qb.x, qb.y, qb.z, qb.w};
        float kv[8] = {ka.x, ka.y, ka.z, ka.w, kb.x, kb.y, kb.z, kb.w};
#pragma unroll
        for (int r = 0; r < 8; ++r)
#pragma unroll
            for (int j = 0; j < 8; ++j)
                s[r * 8 + j] = fmaf(qv[r], kv[j], s[r * 8 + j]);
    }

    // exp (no max: softmax shift-invariant, scores bounded) + partial row sums
    float rs[8];
#pragma unroll
    for (int r = 0; r < 8; ++r) {
        float t = 0.f;
#pragma unroll
        for (int j = 0; j < 8; ++j) {
            float e = __expf(s[r * 8 + j]);
            s[r * 8 + j] = e;
            t += e;
        }
        rs[r] = t;
    }
#pragma unroll
    for (int o = 16; o; o >>= 1)
#pragma unroll
        for (int r = 0; r < 8; ++r)
            rs[r] += __shfl_xor_sync(0xffffffffu, rs[r], o);
    if (lane == 0) {
#pragma unroll
        for (int r = 0; r < 8; ++r) red[warp][r] = rs[r];
    }
    __syncthreads();
    float inv[8];
#pragma unroll
    for (int r = 0; r < 8; ++r)
        inv[r] = 1.0f / (red[tr * 4 + 0][r] + red[tr * 4 + 1][r] +
                         red[tr * 4 + 2][r] + red[tr * 4 + 3][r]);

    size_t obase = ((((size_t)br * Bsz + b) * Hh + h) * Nn + rbase) * (size_t)Nn;
#pragma unroll
    for (int r = 0; r < 8; ++r) {
        size_t rowoff = obase + (size_t)(tr * 8 + r) * Nn;
        float4 va, vb;
        va.x = s[r * 8 + 0] * inv[r]; va.y = s[r * 8 + 1] * inv[r];
        va.z = s[r * 8 + 2] * inv[r]; va.w = s[r * 8 + 3] * inv[r];
        vb.x = s[r * 8 + 4] * inv[r]; vb.y = s[r * 8 + 5] * inv[r];
        vb.z = s[r * 8 + 6] * inv[r]; vb.w = s[r * 8 + 7] * inv[r];
        *(float4*)(out + rowoff + tc * 4)       = va;
        *(float4*)(out + rowoff + 512 + tc * 4) = vb;
    }
}

// ---------------- launcher ----------------
extern "C" void kernel_launch(void* const* d_in, const int* in_sizes, int n_in,
                              void* d_out, int out_size) {
    const float* x      = (const float*)d_in[0];
    const float* edge   = (const float*)d_in[1];
    const float* cedge  = (const float*)d_in[2];
    const float* G      = (const float*)d_in[3];
    const float* CG     = (const float*)d_in[4];
    const float* W_emb  = (const float*)d_in[5];
    const float* b_emb  = (const float*)d_in[6];
    const float* W_q    = (const float*)d_in[7];
    const float* b_q    = (const float*)d_in[8];
    const float* W_k    = (const float*)d_in[9];
    const float* b_k    = (const float*)d_in[10];
    const float* W_eq   = (const float*)d_in[11];
    const float* b_eq   = (const float*)d_in[12];
    const float* W_ek   = (const float*)d_in[13];
    const float* b_ek   = (const float*)d_in[14];
    const float* W_ceq  = (const float*)d_in[15];
    const float* b_ceq  = (const float*)d_in[16];
    const float* W_cek  = (const float*)d_in[17];
    const float* b_cek  = (const float*)d_in[18];
    float* out = (float*)d_out;

    cudaFuncSetAttribute(k_attn, cudaFuncAttributeMaxDynamicSharedMemorySize, 65536);

    k_qk<<<Bsz * Nn, 64>>>(x, W_emb, b_emb, W_q, b_q, W_k, b_k);
    k_edge<<<2048, 256>>>(edge, cedge, W_eq, b_eq, W_ek, b_ek, W_ceq, b_ceq, W_cek, b_cek);
    k_gextra<<<256, 1024>>>(G, CG);
    k_attn<<<4096, 256, 65536>>>(out);
}